// round 17
// baseline (speedup 1.0000x reference)
#include <cuda_runtime.h>
#include <cuda_bf16.h>
#include <cuda_fp16.h>
#include <cstdint>

// ---------------- problem constants ----------------
#define DD   1024
#define EE   8
#define HH   2048
#define NN   8192   // B*T tokens

// GEMM tile config: CTA 128x128, 8 warps (4M x 2N), warp tile 32x64, K-chunk 32
#define TM   128
#define TN   128
#define TK   32
// 1-pass stage: A8K + B8K = 16KB, 6 stages
#define B_OFF 8192
#define STAGE 16384
#define NST   6
#define SMEM_GEMM (NST*STAGE + 96)

// Tiled-plane geometry (all planes 8192B = 128 rows x 64B, swizzled):
//  row byte: m*64 + ((u ^ ((m>>1)&3))<<4) + (k&7)*2,  u = (k>>3)&3

// ---------------- static device scratch ----------------
__device__ int   g_cnt[EE];
__device__ int   g_tok[EE * NN];
__device__ float g_gate[EE * NN];
__device__ __half g_xg  [(size_t)EE * NN * DD];   // [e][mb<64][kc<32][8KB] fp16
__device__ __half g_h   [(size_t)EE * NN * HH];   // [e][mb<64][kc<64][8KB] fp16
__device__ __half g_w1t [(size_t)EE * DD * HH];   // [e][nb<16][kc<32][8KB] fp16
__device__ __half g_w2t [(size_t)EE * HH * DD];   // [e][nb<8][kc<64][8KB] fp16

// ---------------- helpers ----------------
__device__ __forceinline__ uint32_t smem_u32(const void* p) {
    uint32_t a;
    asm("{ .reg .u64 t; cvta.to.shared.u64 t, %1; cvt.u32.u64 %0, t; }" : "=r"(a) : "l"(p));
    return a;
}
__device__ __forceinline__ void ldsm4(uint32_t* r, uint32_t a) {
    asm volatile("ldmatrix.sync.aligned.m8n8.x4.shared.b16 {%0,%1,%2,%3}, [%4];"
                 : "=r"(r[0]), "=r"(r[1]), "=r"(r[2]), "=r"(r[3]) : "r"(a));
}
__device__ __forceinline__ void mma_f16(float* c, const uint32_t* a, uint32_t b0, uint32_t b1) {
    asm volatile("mma.sync.aligned.m16n8k16.row.col.f32.f16.f16.f32 "
                 "{%0,%1,%2,%3}, {%4,%5,%6,%7}, {%8,%9}, {%0,%1,%2,%3};"
                 : "+f"(c[0]), "+f"(c[1]), "+f"(c[2]), "+f"(c[3])
                 : "r"(a[0]), "r"(a[1]), "r"(a[2]), "r"(a[3]), "r"(b0), "r"(b1));
}
__device__ __forceinline__ uint32_t pack2h(float a, float b) {   // fp16 pair
    __half h0 = __float2half_rn(a), h1 = __float2half_rn(b);
    return (uint32_t)__half_as_ushort(h0) | ((uint32_t)__half_as_ushort(h1) << 16);
}
#define MBAR_INIT(a, c) asm volatile("mbarrier.init.shared.b64 [%0], %1;" :: "r"(a), "r"((uint32_t)(c)) : "memory")
#define MBAR_EXPECT_TX(a, tx) asm volatile("mbarrier.arrive.expect_tx.shared.b64 _, [%0], %1;" :: "r"(a), "r"((uint32_t)(tx)) : "memory")
#define MBAR_ARRIVE_REL(a) asm volatile("mbarrier.arrive.release.cta.shared::cta.b64 _, [%0];" :: "r"(a) : "memory")
#define MBAR_WAIT(a, ph) do { \
    uint32_t _m = (a); uint32_t _p = (uint32_t)(ph); uint32_t _d; \
    asm volatile("{\n\t.reg .pred p;\n\tmbarrier.try_wait.parity.acquire.cta.shared::cta.b64 p, [%1], %2;\n\tselp.b32 %0,1,0,p;\n\t}" \
        : "=r"(_d) : "r"(_m), "r"(_p) : "memory"); \
    if (!_d) { \
        asm volatile("{\n\t.reg .pred P1;\n\tWL_%=:\n\tmbarrier.try_wait.parity.acquire.cta.shared::cta.b64 P1, [%0], %1, 0x989680;\n\t@P1 bra.uni WD_%=;\n\tbra.uni WL_%=;\n\tWD_%=:\n\t}" \
            :: "r"(_m), "r"(_p) : "memory"); \
    } } while (0)
__device__ __forceinline__ void bulk_g2s(uint32_t dst, const void* src, uint32_t bytes, uint32_t mbar) {
    asm volatile("cp.async.bulk.shared::cta.global.mbarrier::complete_tx::bytes [%0], [%1], %2, [%3];"
                 :: "r"(dst), "l"(src), "r"(bytes), "r"(mbar) : "memory");
}

// ---------------------------------------------------------------------------
// Kernel 0: zero output + reset counters
// ---------------------------------------------------------------------------
__global__ void zero_kernel(float4* __restrict__ out) {
    int i = blockIdx.x * blockDim.x + threadIdx.x;
    out[i] = make_float4(0.f, 0.f, 0.f, 0.f);
    if (blockIdx.x == 0 && threadIdx.x < EE) g_cnt[threadIdx.x] = 0;
}

// ---------------------------------------------------------------------------
// Kernel 1: FUSED router + gather. One block (256 thr) per token.
// Router summation uses the ORIGINAL strided order (bit-identical logits to
// rounds 1-15); quantization re-reads the row as float4 (L1-hot).
// Plane mapping: thread t -> kc = t>>3, u = (t>>1)&3, halfunit = t&1 (8B).
// ---------------------------------------------------------------------------
__global__ __launch_bounds__(256) void router_gather_kernel(const float* __restrict__ x,
                                                            const float* __restrict__ rw) {
    int n = blockIdx.x, tid = threadIdx.x;
    const float* xr = x + (size_t)n * DD;

    float acc[EE];
#pragma unroll
    for (int e = 0; e < EE; e++) acc[e] = 0.f;
    for (int i = tid; i < DD; i += 256) {
        float xv = xr[i];
#pragma unroll
        for (int e = 0; e < EE; e++) acc[e] += xv * rw[e * DD + i];
    }
#pragma unroll
    for (int e = 0; e < EE; e++)
#pragma unroll
        for (int o = 16; o > 0; o >>= 1) acc[e] += __shfl_down_sync(0xffffffffu, acc[e], o);

    __shared__ float sm[8][EE];
    __shared__ int   sres[4];   // e0, slot0, e1, slot1
    int warp = tid >> 5, lane = tid & 31;
    if (lane == 0)
#pragma unroll
        for (int e = 0; e < EE; e++) sm[warp][e] = acc[e];
    __syncthreads();

    if (tid == 0) {
        float logits[EE];
#pragma unroll
        for (int e = 0; e < EE; e++) {
            float s = 0.f;
#pragma unroll
            for (int w = 0; w < 8; w++) s += sm[w][e];
            logits[e] = s;
        }
        int i0 = 0; float v0 = logits[0];
#pragma unroll
        for (int e = 1; e < EE; e++) if (logits[e] > v0) { v0 = logits[e]; i0 = e; }
        int i1 = 0; float v1 = -3.0e38f;
#pragma unroll
        for (int e = 0; e < EE; e++) if (e != i0 && logits[e] > v1) { v1 = logits[e]; i1 = e; }
        float ex = __expf(v1 - v0);
        float g0 = 1.f / (1.f + ex);
        float g1 = ex * g0;
        int p0 = atomicAdd(&g_cnt[i0], 1);
        g_tok[i0 * NN + p0] = n;  g_gate[i0 * NN + p0] = g0;
        int p1 = atomicAdd(&g_cnt[i1], 1);
        g_tok[i1 * NN + p1] = n;  g_gate[i1 * NN + p1] = g1;
        sres[0] = i0; sres[1] = p0; sres[2] = i1; sres[3] = p1;
    }
    __syncthreads();

    float4 xq = ((const float4*)xr)[tid];
    uint2 hv;
    hv.x = pack2h(xq.x, xq.y);
    hv.y = pack2h(xq.z, xq.w);
    int kc = tid >> 3, u = (tid >> 1) & 3, hu = tid & 1;

#pragma unroll
    for (int k = 0; k < 2; k++) {
        int e    = sres[k * 2];
        int slot = sres[k * 2 + 1];
        int mb = slot >> 7, m = slot & 127;
        size_t plane = (((size_t)e * 64 + mb) * 32 + kc) * 8192;
        uint32_t off = (uint32_t)m * 64 + (uint32_t)((u ^ ((m >> 1) & 3)) << 4) + (uint32_t)(hu * 8);
        *(uint2*)((uint8_t*)g_xg + plane + off) = hv;
    }
}

// ---------------------------------------------------------------------------
// Kernel 2: zero padding rows [cnt, pad128) of each expert's A planes
// ---------------------------------------------------------------------------
__global__ __launch_bounds__(256) void pad_kernel() {
    int e = blockIdx.x;
    int cnt = g_cnt[e];
    int pad = (cnt + 127) & ~127;  if (pad > NN) pad = NN;
    int tid = threadIdx.x;
    int kc = tid >> 3, u = (tid >> 1) & 3, hu = tid & 1;
    for (int slot = cnt + blockIdx.y; slot < pad; slot += gridDim.y) {
        int mb = slot >> 7, m = slot & 127;
        size_t plane = (((size_t)e * 64 + mb) * 32 + kc) * 8192;
        uint32_t off = (uint32_t)m * 64 + (uint32_t)((u ^ ((m >> 1) & 3)) << 4) + (uint32_t)(hu * 8);
        *(uint2*)((uint8_t*)g_xg + plane + off) = make_uint2(0, 0);
    }
}

// ---------------------------------------------------------------------------
// Kernel 3: merged weight transpose/quantize for w1 AND w2.
// grid (256, 2, EE), 256 threads.  y==0: w1 [DD,HH]; y==1: w2 [HH,DD].
// planes [E][nb=C/128][kc=R/32][8192B]
// ---------------------------------------------------------------------------
__global__ __launch_bounds__(256) void wsplit_kernel(const float* __restrict__ w1,
                                                     const float* __restrict__ w2) {
    int which = blockIdx.y, e = blockIdx.z;
    int R, C, kc, nb2;
    const float* w;
    __half* dst;
    if (which == 0) {
        R = DD; C = HH; w = w1; dst = g_w1t;
        kc = blockIdx.x >> 3;          // 32 kc
        nb2 = blockIdx.x & 7;          // 8 nb2
    } else {
        R = HH; C = DD; w = w2; dst = g_w2t;
        kc = blockIdx.x >> 2;          // 64 kc
        nb2 = blockIdx.x & 3;          // 4 nb2
    }
    const float* src = w + (size_t)e * R * C;
    int t = threadIdx.x;
    int n = nb2 * 256 + t;
    float vals[32];
#pragma unroll
    for (int j = 0; j < 32; j++)
        vals[j] = src[(size_t)(kc * 32 + j) * C + n];
    int nb = nb2 * 2 + (t >> 7);
    int m  = t & 127;
    size_t plane = (((size_t)e * (C / 128) + nb) * (R / 32) + kc) * 8192;
    int sw = (m >> 1) & 3;
    uint32_t rbase = (uint32_t)m * 64;
#pragma unroll
    for (int u = 0; u < 4; u++) {
        uint4 h4;
        h4.x = pack2h(vals[u*8+0], vals[u*8+1]);
        h4.y = pack2h(vals[u*8+2], vals[u*8+3]);
        h4.z = pack2h(vals[u*8+4], vals[u*8+5]);
        h4.w = pack2h(vals[u*8+6], vals[u*8+7]);
        uint32_t off = rbase + (uint32_t)((u ^ sw) << 4);
        *(uint4*)((uint8_t*)dst + plane + off) = h4;
    }
}

// ---------------------------------------------------------------------------
// 1-pass fp16 bulk-fed mma.sync grouped GEMM. occ 2, 6-stage mbarrier pipeline.
// D[128x128] += A * B^T. 256 threads (8 warps, 4Mx2N), warp tile 32x64.
// IS_G1: A = xg (K=1024), B = w1t; epilogue relu^2 -> g_h fp16.
// else:  A = g_h (K=2048, split-K 2), B = w2t; gate*atomicAdd scatter.
// ---------------------------------------------------------------------------
template<int KTOT, int KSLICES, bool IS_G1>
__global__ __launch_bounds__(256, 2) void gemm_mma(float* __restrict__ out) {
    constexpr int KC  = (KTOT / KSLICES) / TK;
    constexpr int NBP = (IS_G1 ? HH : DD) / 128;
    constexpr int KCB = KTOT / 32;
    int zz = blockIdx.z;
    int e = zz & (EE - 1);
    int slice = zz >> 3;
    int kc0 = slice * KC;
    int cnt = g_cnt[e];
    int m0  = blockIdx.y * TM;
    if (m0 >= cnt) return;
    int mb  = blockIdx.y;
    int nb  = blockIdx.x;
    int n0  = nb * TN;

    extern __shared__ char smem[];
    uint32_t sb = smem_u32(smem);
    uint32_t fullb  = sb + NST * STAGE;
    uint32_t emptyb = fullb + 48;

    const uint8_t *pA, *pB;
    {
        size_t ap = (((size_t)e * 64 + mb) * KCB) * 8192;
        size_t bp = (((size_t)e * NBP + nb) * KCB) * 8192;
        if (IS_G1) {
            pA = (const uint8_t*)g_xg + ap;
            pB = (const uint8_t*)g_w1t + bp;
        } else {
            pA = (const uint8_t*)g_h + ap;
            pB = (const uint8_t*)g_w2t + bp;
        }
    }

    int tid = threadIdx.x;
    int wid = tid >> 5, lane = tid & 31;

    if (tid == 0) {
#pragma unroll
        for (int s = 0; s < NST; s++) {
            MBAR_INIT(fullb + s * 8, 1);
            MBAR_INIT(emptyb + s * 8, 8);
        }
    }
    __syncthreads();

    auto issue = [&](int j, int s) {
        uint32_t st = sb + (uint32_t)s * STAGE;
        uint32_t mb_s = fullb + s * 8;
        size_t kc = (size_t)(kc0 + j);
        MBAR_EXPECT_TX(mb_s, STAGE);
        bulk_g2s(st,         pA + kc * 8192, 8192, mb_s);
        bulk_g2s(st + B_OFF, pB + kc * 8192, 8192, mb_s);
    };
    if (wid < NST && lane == 0 && wid < KC) issue(wid, wid);

    // ---- warp / lane geometry: 4 warps M x 2 warps N, warp tile 32x64 ----
    int wm = wid & 3;
    int wn = wid >> 2;
    int li = lane >> 3;
    int lr = lane & 7;
    int kadd = li >> 1;
    int rsel = (li & 1) * 8 + lr;

    uint32_t abase[2]; int asw[2];
#pragma unroll
    for (int mt = 0; mt < 2; mt++) {
        int m = wm * 32 + mt * 16 + rsel;
        abase[mt] = (uint32_t)m * 64;
        asw[mt] = (m >> 1) & 3;
    }
    uint32_t bbase[4]; int bsw[4];
#pragma unroll
    for (int p = 0; p < 4; p++) {
        int n = wn * 64 + p * 16 + rsel;
        bbase[p] = (uint32_t)n * 64;
        bsw[p] = (n >> 1) & 3;
    }

    float acc[2][8][4];
#pragma unroll
    for (int a = 0; a < 2; a++)
#pragma unroll
        for (int b = 0; b < 8; b++)
#pragma unroll
            for (int c = 0; c < 4; c++) acc[a][b][c] = 0.f;

    int s = 0;
    uint32_t ph = 0;
    for (int j = 0; j < KC; j++) {
        MBAR_WAIT(fullb + s * 8, ph);
        uint32_t st = sb + (uint32_t)s * STAGE;
#pragma unroll
        for (int kqi = 0; kqi < 2; kqi++) {
            int kq = kqi * 2;
            uint32_t ar[2][4];
#pragma unroll
            for (int mt = 0; mt < 2; mt++) {
                uint32_t off = abase[mt] + (uint32_t)((((kq + kadd) ^ asw[mt])) << 4);
                ldsm4(ar[mt], st + off);
            }
#pragma unroll
            for (int p = 0; p < 4; p++) {
                uint32_t bh[4];
                uint32_t off = bbase[p] + (uint32_t)((((kq + kadd) ^ bsw[p])) << 4);
                ldsm4(bh, st + B_OFF + off);
                if (kqi == 1 && p == 3 && lane == 0) MBAR_ARRIVE_REL(emptyb + s * 8);
#pragma unroll
                for (int mt = 0; mt < 2; mt++) {
#pragma unroll
                    for (int sgl = 0; sgl < 2; sgl++) {
                        float* c = acc[mt][p * 2 + sgl];
                        mma_f16(c, ar[mt], bh[sgl], bh[2 + sgl]);
                    }
                }
            }
        }
        if (wid == s && lane == 0 && j + NST < KC) {
            MBAR_WAIT(emptyb + s * 8, ph);
            issue(j + NST, s);
        }
        if (++s == NST) { s = 0; ph ^= 1; }
    }

    // ---- epilogue ----
    int r4 = lane >> 2, cpair = (lane & 3) * 2;
    if (IS_G1) {
        size_t planeH0 = (((size_t)e * 64 + mb) * 64) * 8192;
#pragma unroll
        for (int mt = 0; mt < 2; mt++) {
#pragma unroll
            for (int q = 0; q < 8; q++) {
                int kcH = (n0 >> 5) + wn * 2 + (q >> 2);
                int u = q & 3;
#pragma unroll
                for (int half = 0; half < 2; half++) {
                    int lm = wm * 32 + mt * 16 + r4 + half * 8;
                    float v0 = acc[mt][q][half * 2 + 0];
                    float v1 = acc[mt][q][half * 2 + 1];
                    v0 = fmaxf(v0, 0.f); v0 *= v0;
                    v1 = fmaxf(v1, 0.f); v1 *= v1;
                    uint32_t hw = pack2h(v0, v1);
                    size_t off = planeH0 + (size_t)kcH * 8192 +
                                 (uint32_t)(lm * 64 + ((u ^ ((lm >> 1) & 3)) << 4) + cpair * 2);
                    *(uint32_t*)((uint8_t*)g_h + off) = hw;
                }
            }
        }
    } else {
#pragma unroll
        for (int mt = 0; mt < 2; mt++) {
            int gm = m0 + wm * 32 + mt * 16;
            int   tokh[2];
            float gth[2];
#pragma unroll
            for (int half = 0; half < 2; half++) {
                int slot = gm + r4 + half * 8;
                bool ok = slot < cnt;
                tokh[half] = ok ? g_tok[e * NN + slot] : -1;
                gth[half]  = ok ? g_gate[e * NN + slot] : 0.f;
            }
#pragma unroll
            for (int q = 0; q < 8; q++) {
                int gn = n0 + wn * 64 + q * 8 + cpair;
#pragma unroll
                for (int half = 0; half < 2; half++) {
                    if (tokh[half] >= 0) {
                        float* orow = out + (size_t)tokh[half] * DD + gn;
                        atomicAdd(orow,     gth[half] * acc[mt][q][half * 2 + 0]);
                        atomicAdd(orow + 1, gth[half] * acc[mt][q][half * 2 + 1]);
                    }
                }
            }
        }
    }
}

// ---------------------------------------------------------------------------
extern "C" void kernel_launch(void* const* d_in, const int* in_sizes, int n_in,
                              void* d_out, int out_size) {
    const float* x  = (const float*)d_in[0];   // (B,T,D)
    const float* rw = (const float*)d_in[1];   // (E,D)
    const float* w1 = (const float*)d_in[2];   // (E,D,H)
    const float* w2 = (const float*)d_in[3];   // (E,H,D)
    float* out = (float*)d_out;                // (B,T,D) fp32

    cudaFuncSetAttribute(gemm_mma<DD, 1, true>,  cudaFuncAttributeMaxDynamicSharedMemorySize, SMEM_GEMM);
    cudaFuncSetAttribute(gemm_mma<HH, 2, false>, cudaFuncAttributeMaxDynamicSharedMemorySize, SMEM_GEMM);

    int zblocks = out_size / (4 * 256);
    zero_kernel<<<zblocks, 256>>>((float4*)out);
    router_gather_kernel<<<NN, 256>>>(x, rw);
    pad_kernel<<<dim3(EE, 16), 256>>>();
    wsplit_kernel<<<dim3(256, 2, EE), 256>>>(w1, w2);
    gemm_mma<DD, 1, true><<<dim3(HH / TN, NN / TM, EE), 256, SMEM_GEMM>>>(nullptr);
    gemm_mma<HH, 2, false><<<dim3(DD / TN, NN / TM, EE * 2), 256, SMEM_GEMM>>>(out);
}